// round 1
// baseline (speedup 1.0000x reference)
#include <cuda_runtime.h>
#include <cuda_bf16.h>
#include <math.h>

// Problem constants
#define N_NODES 8192
#define D 128           // D_IN == D_OUT == 128
#define EPS 1e-6f

// Scratch (no allocation allowed -> __device__ globals)
__device__ float g_dinv[N_NODES];          // 32 KB
__device__ float g_z[N_NODES * D];         // 4 MB : dinv[j] * (x @ W^T)[j,:]

// ---------------------------------------------------------------------------
// Kernel 1: row sums of adj -> dinv = rsqrt(sum + eps)
// One block per row, 256 threads, float4 loads.
// ---------------------------------------------------------------------------
__global__ void rowsum_kernel(const float* __restrict__ adj, float* __restrict__ dinv) {
    int row = blockIdx.x;
    const float4* p = reinterpret_cast<const float4*>(adj + (size_t)row * N_NODES);
    float s = 0.f;
    for (int j = threadIdx.x; j < N_NODES / 4; j += 256) {
        float4 v = p[j];
        s += (v.x + v.y) + (v.z + v.w);
    }
    // warp reduce
    #pragma unroll
    for (int off = 16; off > 0; off >>= 1)
        s += __shfl_down_sync(0xffffffffu, s, off);
    __shared__ float warp_sums[8];
    int lane = threadIdx.x & 31, wid = threadIdx.x >> 5;
    if (lane == 0) warp_sums[wid] = s;
    __syncthreads();
    if (wid == 0) {
        float t = (lane < 8) ? warp_sums[lane] : 0.f;
        #pragma unroll
        for (int off = 4; off > 0; off >>= 1)
            t += __shfl_down_sync(0xffffffffu, t, off);
        if (lane == 0) dinv[row] = rsqrtf(t + EPS);
    }
}

// ---------------------------------------------------------------------------
// Kernel 2: z[r, c] = dinv[r] * sum_k x[r,k] * W[c,k]
// One block per row, 128 threads (one per output column). W cached in L1/L2.
// ---------------------------------------------------------------------------
__global__ void xw_kernel(const float* __restrict__ x, const float* __restrict__ W,
                          const float* __restrict__ dinv, float* __restrict__ z) {
    int r = blockIdx.x;
    int c = threadIdx.x;
    __shared__ float xr[D];
    xr[c] = x[(size_t)r * D + c];
    __syncthreads();
    const float4* wrow = reinterpret_cast<const float4*>(W + (size_t)c * D);
    const float4* xv   = reinterpret_cast<const float4*>(xr);
    float s = 0.f;
    #pragma unroll
    for (int k = 0; k < D / 4; k++) {
        float4 wv = __ldg(&wrow[k]);
        float4 xf = xv[k];
        s += xf.x * wv.x + xf.y * wv.y + xf.z * wv.z + xf.w * wv.w;
    }
    z[(size_t)r * D + c] = s * dinv[r];
}

// ---------------------------------------------------------------------------
// Kernel 3: out[i, c] = dinv[i] * sum_j adj[i,j] * z[j,c] + b[c]
// Tiled SGEMM: M=8192, N=128, K=8192. BM=64, BN=128, BK=16.
// 256 threads, 4x8 micro-tile per thread, register prefetch of next tile.
// Grid = 128 blocks.
// ---------------------------------------------------------------------------
#define BM 64
#define BN 128
#define BK 16
#define APAD 4

__global__ __launch_bounds__(256, 1)
void gcn_gemm_kernel(const float* __restrict__ adj, const float* __restrict__ z,
                     const float* __restrict__ dinv, const float* __restrict__ bias,
                     float* __restrict__ out) {
    __shared__ float As[BK][BM + APAD];   // transposed A tile: As[k][m]
    __shared__ float Bs[BK][BN];

    const int tid = threadIdx.x;
    const int block_row = blockIdx.x * BM;

    const int tx = tid & 15;   // 0..15 : column group (8 cols each)
    const int ty = tid >> 4;   // 0..15 : row group (4 rows each)

    // A tile load mapping: 64 rows x 16 k = 256 float4, one per thread
    const int a_row  = tid >> 2;          // 0..63
    const int a_col4 = (tid & 3) << 2;    // 0,4,8,12
    // B tile load mapping: 16 k x 128 c = 512 float4, two per thread
    const int b_k = tid >> 5;             // 0..7  (and +8)
    const int b_c = (tid & 31) << 2;      // 0..124

    const size_t lda = N_NODES;

    float acc[4][8];
    #pragma unroll
    for (int i = 0; i < 4; i++)
        #pragma unroll
        for (int j = 0; j < 8; j++) acc[i][j] = 0.f;

    // initial prefetch
    float4 av  = *reinterpret_cast<const float4*>(adj + (size_t)(block_row + a_row) * lda + a_col4);
    float4 bv0 = *reinterpret_cast<const float4*>(z + (size_t)(b_k)     * D + b_c);
    float4 bv1 = *reinterpret_cast<const float4*>(z + (size_t)(b_k + 8) * D + b_c);

    for (int k0 = 0; k0 < N_NODES; k0 += BK) {
        // stage current regs into smem
        As[a_col4 + 0][a_row] = av.x;
        As[a_col4 + 1][a_row] = av.y;
        As[a_col4 + 2][a_row] = av.z;
        As[a_col4 + 3][a_row] = av.w;
        *reinterpret_cast<float4*>(&Bs[b_k][b_c])     = bv0;
        *reinterpret_cast<float4*>(&Bs[b_k + 8][b_c]) = bv1;
        __syncthreads();

        // prefetch next tile (redundant wrap-around load on final iter; harmless)
        int kn = (k0 + BK < N_NODES) ? (k0 + BK) : 0;
        av  = *reinterpret_cast<const float4*>(adj + (size_t)(block_row + a_row) * lda + kn + a_col4);
        bv0 = *reinterpret_cast<const float4*>(z + (size_t)(kn + b_k)     * D + b_c);
        bv1 = *reinterpret_cast<const float4*>(z + (size_t)(kn + b_k + 8) * D + b_c);

        // compute
        #pragma unroll
        for (int k = 0; k < BK; k++) {
            float a[4], bb[8];
            float4 a4 = *reinterpret_cast<const float4*>(&As[k][ty << 2]);
            a[0] = a4.x; a[1] = a4.y; a[2] = a4.z; a[3] = a4.w;
            float4 b4l = *reinterpret_cast<const float4*>(&Bs[k][tx << 3]);
            float4 b4h = *reinterpret_cast<const float4*>(&Bs[k][(tx << 3) + 4]);
            bb[0] = b4l.x; bb[1] = b4l.y; bb[2] = b4l.z; bb[3] = b4l.w;
            bb[4] = b4h.x; bb[5] = b4h.y; bb[6] = b4h.z; bb[7] = b4h.w;
            #pragma unroll
            for (int i = 0; i < 4; i++)
                #pragma unroll
                for (int j = 0; j < 8; j++)
                    acc[i][j] += a[i] * bb[j];
        }
        __syncthreads();
    }

    // epilogue: scale by dinv[row], add bias
    const int cbase = tx << 3;
    float4 bL, bH;
    bL.x = __ldg(&bias[cbase + 0]); bL.y = __ldg(&bias[cbase + 1]);
    bL.z = __ldg(&bias[cbase + 2]); bL.w = __ldg(&bias[cbase + 3]);
    bH.x = __ldg(&bias[cbase + 4]); bH.y = __ldg(&bias[cbase + 5]);
    bH.z = __ldg(&bias[cbase + 6]); bH.w = __ldg(&bias[cbase + 7]);

    #pragma unroll
    for (int i = 0; i < 4; i++) {
        int r = block_row + (ty << 2) + i;
        float di = dinv[r];
        float4 o0, o1;
        o0.x = acc[i][0] * di + bL.x;
        o0.y = acc[i][1] * di + bL.y;
        o0.z = acc[i][2] * di + bL.z;
        o0.w = acc[i][3] * di + bL.w;
        o1.x = acc[i][4] * di + bH.x;
        o1.y = acc[i][5] * di + bH.y;
        o1.z = acc[i][6] * di + bH.z;
        o1.w = acc[i][7] * di + bH.w;
        *reinterpret_cast<float4*>(out + (size_t)r * D + cbase)     = o0;
        *reinterpret_cast<float4*>(out + (size_t)r * D + cbase + 4) = o1;
    }
}

// ---------------------------------------------------------------------------
// kernel_launch: inputs per metadata order: x, adj, W, b
// ---------------------------------------------------------------------------
extern "C" void kernel_launch(void* const* d_in, const int* in_sizes, int n_in,
                              void* d_out, int out_size) {
    const float* x   = (const float*)d_in[0];
    const float* adj = (const float*)d_in[1];
    const float* W   = (const float*)d_in[2];
    const float* b   = (const float*)d_in[3];
    float* out = (float*)d_out;

    float* dinv;
    float* z;
    cudaGetSymbolAddress((void**)&dinv, g_dinv);
    cudaGetSymbolAddress((void**)&z, g_z);

    rowsum_kernel<<<N_NODES, 256>>>(adj, dinv);
    xw_kernel<<<N_NODES, D>>>(x, W, dinv, z);
    gcn_gemm_kernel<<<N_NODES / BM, 256>>>(adj, z, dinv, b, out);
}

// round 3
// speedup vs baseline: 3.0448x; 3.0448x over previous
#include <cuda_runtime.h>
#include <cuda_bf16.h>
#include <cstdint>

// ---------------- problem constants ----------------
#define N_NODES 8192
#define DFEAT   128
#define EPS     1e-6f

// ---------------- GEMM tiling ----------------
#define KSPLIT   2
#define KHALF    (N_NODES / KSPLIT)     // 4096
#define BM       128
#define KSTAGE   32
#define NSTAGES  (KHALF / KSTAGE)       // 128
#define ROWS_E   40                     // smem row stride in bf16 elems (32 + 8 pad)
#define ROWBYTES 80
#define TILEB    (BM * ROWBYTES)        // 10240 bytes per 128x32 bf16 tile
#define AH_OFF   0
#define AL_OFF   (1 * TILEB)
#define BH_OFF   (2 * TILEB)
#define BL_OFF   (3 * TILEB)
#define BUFB     (4 * TILEB)            // 40960
#define SMEM_DYN (2 * BUFB)             // 81920 (double buffer)

// ---------------- scratch (no allocation allowed) ----------------
__device__ float                        g_dinv[N_NODES];
__device__ __align__(16) __nv_bfloat16  g_zT_hi[DFEAT * N_NODES];   // [c][k]
__device__ __align__(16) __nv_bfloat16  g_zT_lo[DFEAT * N_NODES];
__device__ __align__(16) float          g_part[KSPLIT][N_NODES * DFEAT];

// ---------------- helpers ----------------
static __device__ __forceinline__ uint32_t smem_u32(const void* p) {
    uint32_t a;
    asm("{ .reg .u64 t; cvta.to.shared.u64 t, %1; cvt.u32.u64 %0, t; }" : "=r"(a) : "l"(p));
    return a;
}

#define LDSM4(r, addr) \
    asm volatile("ldmatrix.sync.aligned.m8n8.x4.shared.b16 {%0,%1,%2,%3}, [%4];" \
        : "=r"((r)[0]), "=r"((r)[1]), "=r"((r)[2]), "=r"((r)[3]) : "r"(addr))

#define MMA16816(d, a, b0, b1) \
    asm volatile("mma.sync.aligned.m16n8k16.row.col.f32.bf16.bf16.f32 " \
        "{%0,%1,%2,%3}, {%4,%5,%6,%7}, {%8,%9}, {%0,%1,%2,%3};" \
        : "+f"((d)[0]), "+f"((d)[1]), "+f"((d)[2]), "+f"((d)[3]) \
        : "r"((a)[0]), "r"((a)[1]), "r"((a)[2]), "r"((a)[3]), "r"(b0), "r"(b1))

static __device__ __forceinline__ void cvt_split4(float4 v, uint2& h, uint2& l) {
    __nv_bfloat16 h0 = __float2bfloat16_rn(v.x);
    __nv_bfloat16 h1 = __float2bfloat16_rn(v.y);
    __nv_bfloat16 h2 = __float2bfloat16_rn(v.z);
    __nv_bfloat16 h3 = __float2bfloat16_rn(v.w);
    __nv_bfloat16 l0 = __float2bfloat16_rn(v.x - __bfloat162float(h0));
    __nv_bfloat16 l1 = __float2bfloat16_rn(v.y - __bfloat162float(h1));
    __nv_bfloat16 l2 = __float2bfloat16_rn(v.z - __bfloat162float(h2));
    __nv_bfloat16 l3 = __float2bfloat16_rn(v.w - __bfloat162float(h3));
    h.x = (uint32_t)__bfloat16_as_ushort(h0) | ((uint32_t)__bfloat16_as_ushort(h1) << 16);
    h.y = (uint32_t)__bfloat16_as_ushort(h2) | ((uint32_t)__bfloat16_as_ushort(h3) << 16);
    l.x = (uint32_t)__bfloat16_as_ushort(l0) | ((uint32_t)__bfloat16_as_ushort(l1) << 16);
    l.y = (uint32_t)__bfloat16_as_ushort(l2) | ((uint32_t)__bfloat16_as_ushort(l3) << 16);
}

// ---------------------------------------------------------------------------
// Kernel 1: dinv[i] = rsqrt(rowsum(adj_i) + eps)
// ---------------------------------------------------------------------------
__global__ void rowsum_kernel(const float* __restrict__ adj, float* __restrict__ dinv) {
    int row = blockIdx.x;
    const float4* p = reinterpret_cast<const float4*>(adj + (size_t)row * N_NODES);
    float s = 0.f;
    for (int j = threadIdx.x; j < N_NODES / 4; j += 256) {
        float4 v = p[j];
        s += (v.x + v.y) + (v.z + v.w);
    }
    #pragma unroll
    for (int off = 16; off > 0; off >>= 1) s += __shfl_down_sync(0xffffffffu, s, off);
    __shared__ float ws[8];
    int lane = threadIdx.x & 31, wid = threadIdx.x >> 5;
    if (lane == 0) ws[wid] = s;
    __syncthreads();
    if (wid == 0) {
        float t = (lane < 8) ? ws[lane] : 0.f;
        #pragma unroll
        for (int off = 4; off > 0; off >>= 1) t += __shfl_down_sync(0xffffffffu, t, off);
        if (lane == 0) dinv[row] = rsqrtf(t + EPS);
    }
}

// ---------------------------------------------------------------------------
// Kernel 2: z^T (hi/lo bf16 split), z[r][c] = dinv[r] * dot(x[r,:], W[c,:])
// Writes z^T in [c][k] layout (n-major, k contiguous).
// ---------------------------------------------------------------------------
__global__ __launch_bounds__(256) void xw_kernel(
    const float* __restrict__ x, const float* __restrict__ W, const float* __restrict__ dinv,
    __nv_bfloat16* __restrict__ zh, __nv_bfloat16* __restrict__ zl)
{
    __shared__ float xs[8][DFEAT];
    __shared__ float zs[DFEAT][8];
    int r0 = blockIdx.x * 8;
    int t = threadIdx.x;
    for (int i = t; i < 8 * DFEAT; i += 256)
        xs[i >> 7][i & 127] = x[(size_t)r0 * DFEAT + i];
    __syncthreads();

    int c = t & 127, rh = t >> 7;
    const float4* wr = reinterpret_cast<const float4*>(W + (size_t)c * DFEAT);
    float acc[4] = {0.f, 0.f, 0.f, 0.f};
    #pragma unroll 8
    for (int k4 = 0; k4 < DFEAT / 4; k4++) {
        float4 wv = __ldg(&wr[k4]);
        #pragma unroll
        for (int j = 0; j < 4; j++) {
            const float* xr = &xs[rh * 4 + j][k4 * 4];
            acc[j] += wv.x * xr[0] + wv.y * xr[1] + wv.z * xr[2] + wv.w * xr[3];
        }
    }
    #pragma unroll
    for (int j = 0; j < 4; j++)
        zs[c][rh * 4 + j] = acc[j] * dinv[r0 + rh * 4 + j];
    __syncthreads();

    if (t < 128) {
        uint2 h0, l0, h1, l1;
        float4 v0 = make_float4(zs[t][0], zs[t][1], zs[t][2], zs[t][3]);
        float4 v1 = make_float4(zs[t][4], zs[t][5], zs[t][6], zs[t][7]);
        cvt_split4(v0, h0, l0);
        cvt_split4(v1, h1, l1);
        size_t off = (size_t)t * N_NODES + r0;
        *reinterpret_cast<uint4*>(zh + off) = make_uint4(h0.x, h0.y, h1.x, h1.y);
        *reinterpret_cast<uint4*>(zl + off) = make_uint4(l0.x, l0.y, l1.x, l1.y);
    }
}

// ---------------------------------------------------------------------------
// Kernel 3: bf16 3-term split GEMM via mma.sync (m16n8k16) + ldmatrix.
// part[kz][m][c] = sum_{k in half kz} adj[m][k] * z[k][c]
// Grid: 64 M-tiles x 2 K-halves = 128 CTAs, 512 threads (16 warps, 32x32 tiles)
// ---------------------------------------------------------------------------
__global__ __launch_bounds__(512, 1) void gcn_mma_kernel(
    const float* __restrict__ adj,
    const __nv_bfloat16* __restrict__ zh,
    const __nv_bfloat16* __restrict__ zl,
    float* __restrict__ part)
{
    extern __shared__ char smem[];
    const uint32_t sbase = smem_u32(smem);

    const int tid  = threadIdx.x;
    const int lane = tid & 31;
    const int wid  = tid >> 5;

    const int mt = blockIdx.x >> 1;
    const int kz = blockIdx.x & 1;
    const int m0 = mt * BM;
    const int kbase = kz * KHALF;
    float* pout = part + (size_t)kz * (N_NODES * DFEAT);

    // ---- global load index precompute ----
    const int ar0 = tid >> 3;               // A rows: ar0 and ar0+64
    const int ak0 = (tid & 7) << 2;         // k offset (floats), 0..28
    const int bn  = tid >> 2;               // B row (n), 0..127
    const int bk8 = (tid & 3) << 3;         // k offset (elems), 0..24

    const float* aptr0 = adj + (size_t)(m0 + ar0) * N_NODES + kbase + ak0;
    const float* aptr1 = aptr0 + (size_t)64 * N_NODES;
    const __nv_bfloat16* bhp = zh + (size_t)bn * N_NODES + kbase + bk8;
    const __nv_bfloat16* blp = zl + (size_t)bn * N_NODES + kbase + bk8;

    const uint32_t aoff = (uint32_t)(ar0 * ROWBYTES + ak0 * 2);
    const uint32_t boff = (uint32_t)(bn * ROWBYTES + bk8 * 2);

    // ---- ldmatrix address precompute ----
    const int wm = wid >> 2, wn = wid & 3;
    const int idx = lane >> 3;              // 0..3 : which 8x8 within x4
    const uint32_t a_lm = (uint32_t)((wm * 32 + (idx & 1) * 8 + (lane & 7)) * ROWBYTES
                                     + ((idx >> 1) * 8) * 2);
    const uint32_t b_lm = (uint32_t)((wn * 32 + (idx >> 1) * 8 + (lane & 7)) * ROWBYTES
                                     + ((idx & 1) * 8) * 2);

    float d[2][4][4];
    #pragma unroll
    for (int i = 0; i < 2; i++)
        #pragma unroll
        for (int j = 0; j < 4; j++)
            #pragma unroll
            for (int q = 0; q < 4; q++) d[i][j][q] = 0.f;

    // prefetch stage 0
    float4 aPre0 = *reinterpret_cast<const float4*>(aptr0);
    float4 aPre1 = *reinterpret_cast<const float4*>(aptr1);
    uint4  bhPre = *reinterpret_cast<const uint4*>(bhp);
    uint4  blPre = *reinterpret_cast<const uint4*>(blp);

    for (int s = 0; s < NSTAGES; s++) {
        const uint32_t bufb = (uint32_t)((s & 1) * BUFB);
        char* cbuf = smem + bufb;

        // ---- stage regs -> smem (with fp32 -> bf16 hi/lo split for A) ----
        uint2 h, l;
        cvt_split4(aPre0, h, l);
        *reinterpret_cast<uint2*>(cbuf + AH_OFF + aoff) = h;
        *reinterpret_cast<uint2*>(cbuf + AL_OFF + aoff) = l;
        cvt_split4(aPre1, h, l);
        *reinterpret_cast<uint2*>(cbuf + AH_OFF + aoff + 64 * ROWBYTES) = h;
        *reinterpret_cast<uint2*>(cbuf + AL_OFF + aoff + 64 * ROWBYTES) = l;
        *reinterpret_cast<uint4*>(cbuf + BH_OFF + boff) = bhPre;
        *reinterpret_cast<uint4*>(cbuf + BL_OFF + boff) = blPre;
        __syncthreads();

        // ---- prefetch next stage ----
        if (s + 1 < NSTAGES) {
            const int ko = (s + 1) * KSTAGE;
            aPre0 = *reinterpret_cast<const float4*>(aptr0 + ko);
            aPre1 = *reinterpret_cast<const float4*>(aptr1 + ko);
            bhPre = *reinterpret_cast<const uint4*>(bhp + ko);
            blPre = *reinterpret_cast<const uint4*>(blp + ko);
        }

        // ---- MMA on this buffer ----
        const uint32_t sb = sbase + bufb;
        #pragma unroll
        for (int kk = 0; kk < 2; kk++) {
            uint32_t ah[2][4], al[2][4], bh[2][4], bl[2][4];
            #pragma unroll
            for (int mf = 0; mf < 2; mf++) {
                uint32_t addr = sb + AH_OFF + a_lm + mf * (16 * ROWBYTES) + kk * 32;
                LDSM4(ah[mf], addr);
                LDSM4(al[mf], addr + TILEB);
            }
            #pragma unroll
            for (int nf2 = 0; nf2 < 2; nf2++) {
                uint32_t addr = sb + BH_OFF + b_lm + nf2 * (16 * ROWBYTES) + kk * 32;
                LDSM4(bh[nf2], addr);
                LDSM4(bl[nf2], addr + TILEB);
            }
            #pragma unroll
            for (int mf = 0; mf < 2; mf++) {
                #pragma unroll
                for (int nf = 0; nf < 4; nf++) {
                    uint32_t b0h = bh[nf >> 1][(nf & 1) * 2], b1h = bh[nf >> 1][(nf & 1) * 2 + 1];
                    uint32_t b0l = bl[nf >> 1][(nf & 1) * 2], b1l = bl[nf >> 1][(nf & 1) * 2 + 1];
                    MMA16816(d[mf][nf], ah[mf], b0h, b1h);
                    MMA16816(d[mf][nf], ah[mf], b0l, b1l);
                    MMA16816(d[mf][nf], al[mf], b0h, b1h);
                }
            }
        }
        __syncthreads();
    }

    // ---- epilogue: write partials ----
    const int g = lane >> 2, tg = lane & 3;
    #pragma unroll
    for (int mf = 0; mf < 2; mf++) {
        #pragma unroll
        for (int nf = 0; nf < 4; nf++) {
            int m = m0 + wm * 32 + mf * 16 + g;
            int n = wn * 32 + nf * 8 + tg * 2;
            float* o = pout + (size_t)m * DFEAT + n;
            *reinterpret_cast<float2*>(o) = make_float2(d[mf][nf][0], d[mf][nf][1]);
            *reinterpret_cast<float2*>(o + 8 * DFEAT) = make_float2(d[mf][nf][2], d[mf][nf][3]);
        }
    }
}

// ---------------------------------------------------------------------------
// Kernel 4: out[m][c] = dinv[m] * (p0 + p1)[m][c] + b[c]
// ---------------------------------------------------------------------------
__global__ void reduce_kernel(const float* __restrict__ p0, const float* __restrict__ p1,
                              const float* __restrict__ dinv, const float* __restrict__ bias,
                              float* __restrict__ out)
{
    int idx = blockIdx.x * blockDim.x + threadIdx.x;
    int e = idx << 2;
    int m = e >> 7, c = e & 127;
    float4 a = reinterpret_cast<const float4*>(p0)[idx];
    float4 b = reinterpret_cast<const float4*>(p1)[idx];
    float di = __ldg(&dinv[m]);
    float4 bb = *reinterpret_cast<const float4*>(bias + c);
    float4 o;
    o.x = di * (a.x + b.x) + bb.x;
    o.y = di * (a.y + b.y) + bb.y;
    o.z = di * (a.z + b.z) + bb.z;
    o.w = di * (a.w + b.w) + bb.w;
    reinterpret_cast<float4*>(out)[idx] = o;
}

// ---------------------------------------------------------------------------
// kernel_launch: inputs per metadata order: x, adj, W, b
// ---------------------------------------------------------------------------
extern "C" void kernel_launch(void* const* d_in, const int* in_sizes, int n_in,
                              void* d_out, int out_size) {
    const float* x   = (const float*)d_in[0];
    const float* adj = (const float*)d_in[1];
    const float* W   = (const float*)d_in[2];
    const float* b   = (const float*)d_in[3];
    float* out = (float*)d_out;

    float* dinv;       cudaGetSymbolAddress((void**)&dinv, g_dinv);
    __nv_bfloat16* zh; cudaGetSymbolAddress((void**)&zh, g_zT_hi);
    __nv_bfloat16* zl; cudaGetSymbolAddress((void**)&zl, g_zT_lo);
    float* part;       cudaGetSymbolAddress((void**)&part, g_part);

    cudaFuncSetAttribute(gcn_mma_kernel, cudaFuncAttributeMaxDynamicSharedMemorySize, SMEM_DYN);

    rowsum_kernel<<<N_NODES, 256>>>(adj, dinv);
    xw_kernel<<<N_NODES / 8, 256>>>(x, W, dinv, zh, zl);
    gcn_mma_kernel<<<(N_NODES / BM) * KSPLIT, 512, SMEM_DYN>>>(adj, zh, zl, part);
    reduce_kernel<<<(N_NODES * DFEAT / 4) / 256, 256>>>(part, part + (size_t)N_NODES * DFEAT,
                                                        dinv, b, out);
}

// round 5
// speedup vs baseline: 5.1802x; 1.7013x over previous
#include <cuda_runtime.h>
#include <cuda_fp16.h>
#include <cstdint>

// ---------------- problem constants ----------------
#define N_NODES 8192
#define DFEAT   128
#define EPS     1e-6f

// ---------------- GEMM tiling ----------------
#define KSPLIT   2
#define KHALF    (N_NODES / KSPLIT)     // 4096
#define BM       128
#define KSTAGE   64
#define NSTAGES  (KHALF / KSTAGE)       // 64
#define ROWB     144                    // smem row stride bytes (64 fp16 = 128B + 16 pad)
#define ATILE    (BM * ROWB)            // 18432
#define BTILE    (DFEAT * ROWB)         // 18432
#define BUFB     (ATILE + BTILE)        // 36864
#define SMEM_DYN (2 * BUFB)             // 73728

// ---------------- scratch (no allocation allowed) ----------------
__device__ float                   g_dinv[N_NODES];
__device__ __align__(16) __half    g_zT[DFEAT * N_NODES];           // [c][k] fp16
__device__ __align__(16) float     g_part[KSPLIT][N_NODES * DFEAT];

// ---------------- helpers ----------------
static __device__ __forceinline__ uint32_t smem_u32(const void* p) {
    uint32_t a;
    asm("{ .reg .u64 t; cvta.to.shared.u64 t, %1; cvt.u32.u64 %0, t; }" : "=r"(a) : "l"(p));
    return a;
}

#define LDSM4(r, addr) \
    asm volatile("ldmatrix.sync.aligned.m8n8.x4.shared.b16 {%0,%1,%2,%3}, [%4];" \
        : "=r"((r)[0]), "=r"((r)[1]), "=r"((r)[2]), "=r"((r)[3]) : "r"(addr))

#define MMAF16(d, a, b0, b1) \
    asm volatile("mma.sync.aligned.m16n8k16.row.col.f32.f16.f16.f32 " \
        "{%0,%1,%2,%3}, {%4,%5,%6,%7}, {%8,%9}, {%0,%1,%2,%3};" \
        : "+f"((d)[0]), "+f"((d)[1]), "+f"((d)[2]), "+f"((d)[3]) \
        : "r"((a)[0]), "r"((a)[1]), "r"((a)[2]), "r"((a)[3]), "r"(b0), "r"(b1))

static __device__ __forceinline__ uint2 f4_to_h4(float4 v) {
    __half2 p0 = __float22half2_rn(make_float2(v.x, v.y));
    __half2 p1 = __float22half2_rn(make_float2(v.z, v.w));
    uint2 r;
    r.x = *reinterpret_cast<uint32_t*>(&p0);
    r.y = *reinterpret_cast<uint32_t*>(&p1);
    return r;
}

// ---------------------------------------------------------------------------
// Kernel 1: dinv[i] = rsqrt(rowsum(adj_i) + eps)
// ---------------------------------------------------------------------------
__global__ void rowsum_kernel(const float* __restrict__ adj, float* __restrict__ dinv) {
    int row = blockIdx.x;
    const float4* p = reinterpret_cast<const float4*>(adj + (size_t)row * N_NODES);
    float s = 0.f;
    for (int j = threadIdx.x; j < N_NODES / 4; j += 256) {
        float4 v = p[j];
        s += (v.x + v.y) + (v.z + v.w);
    }
    #pragma unroll
    for (int off = 16; off > 0; off >>= 1) s += __shfl_down_sync(0xffffffffu, s, off);
    __shared__ float ws[8];
    int lane = threadIdx.x & 31, wid = threadIdx.x >> 5;
    if (lane == 0) ws[wid] = s;
    __syncthreads();
    if (wid == 0) {
        float t = (lane < 8) ? ws[lane] : 0.f;
        #pragma unroll
        for (int off = 4; off > 0; off >>= 1) t += __shfl_down_sync(0xffffffffu, t, off);
        if (lane == 0) dinv[row] = rsqrtf(t + EPS);
    }
}

// ---------------------------------------------------------------------------
// Kernel 2: zT[c][k] = fp16( dinv[k] * dot(x[k,:], W[c,:]) )   (fp32 math)
// ---------------------------------------------------------------------------
__global__ __launch_bounds__(256) void xw_kernel(
    const float* __restrict__ x, const float* __restrict__ W, const float* __restrict__ dinv,
    __half* __restrict__ zT)
{
    __shared__ float xs[8][DFEAT];
    __shared__ float zs[DFEAT][8];
    int r0 = blockIdx.x * 8;
    int t = threadIdx.x;
    for (int i = t; i < 8 * DFEAT; i += 256)
        xs[i >> 7][i & 127] = x[(size_t)r0 * DFEAT + i];
    __syncthreads();

    int c = t & 127, rh = t >> 7;
    const float4* wr = reinterpret_cast<const float4*>(W + (size_t)c * DFEAT);
    float acc[4] = {0.f, 0.f, 0.f, 0.f};
    #pragma unroll 8
    for (int k4 = 0; k4 < DFEAT / 4; k4++) {
        float4 wv = __ldg(&wr[k4]);
        #pragma unroll
        for (int j = 0; j < 4; j++) {
            const float* xr = &xs[rh * 4 + j][k4 * 4];
            acc[j] += wv.x * xr[0] + wv.y * xr[1] + wv.z * xr[2] + wv.w * xr[3];
        }
    }
    #pragma unroll
    for (int j = 0; j < 4; j++)
        zs[c][rh * 4 + j] = acc[j] * dinv[r0 + rh * 4 + j];
    __syncthreads();

    if (t < 128) {
        uint2 h0 = f4_to_h4(make_float4(zs[t][0], zs[t][1], zs[t][2], zs[t][3]));
        uint2 h1 = f4_to_h4(make_float4(zs[t][4], zs[t][5], zs[t][6], zs[t][7]));
        *reinterpret_cast<uint4*>(zT + (size_t)t * N_NODES + r0) = make_uint4(h0.x, h0.y, h1.x, h1.y);
    }
}

// ---------------------------------------------------------------------------
// Kernel 3: single-term fp16 GEMM via mma.sync m16n8k16.
// part[kz][m][c] = sum_{k in half kz} adj[m][k] * z[k][c]
// Grid: 64 M-tiles x 2 K-halves = 128 CTAs. 256 threads = 8 warps,
// warp grid 4(m) x 2(n), warp tile 32m x 64n. Double-buffered smem, KSTAGE=64.
// ---------------------------------------------------------------------------
__global__ __launch_bounds__(256, 1) void gcn_mma_kernel(
    const float* __restrict__ adj,
    const __half* __restrict__ zT,
    float* __restrict__ part)
{
    extern __shared__ char smem[];
    const uint32_t sbase = smem_u32(smem);

    const int tid  = threadIdx.x;
    const int lane = tid & 31;
    const int wid  = tid >> 5;
    const int wm   = wid >> 1;          // 0..3
    const int wn   = wid & 1;           // 0..1

    const int mt = blockIdx.x >> 1;
    const int kz = blockIdx.x & 1;
    const int m0 = mt * BM;
    const int kbase = kz * KHALF;
    float* pout = part + (size_t)kz * (N_NODES * DFEAT);

    // ---- global load mapping (fully coalesced) ----
    // A: 128 rows x 64 floats = 2048 float4; 8 per thread. flat = tid + i*256
    //    row = flat/16, kq = flat%16 (float4 units)
    const float* aBase = adj + (size_t)(m0 + (tid >> 4)) * N_NODES + kbase + ((tid & 15) << 2);
    const uint32_t aSoff = (uint32_t)((tid >> 4) * ROWB + (tid & 15) * 8);
    // B: 128 n-rows x 64 halves = 1024 uint4; 4 per thread. n = flat/8, k8 = flat%8
    const __half* bBase = zT + (size_t)(tid >> 3) * N_NODES + kbase + ((tid & 7) << 3);
    const uint32_t bSoff = (uint32_t)((tid >> 3) * ROWB + (tid & 7) * 16);

    // ---- ldmatrix address precompute ----
    const int idx = lane >> 3;   // 0..3
    const uint32_t a_lm = (uint32_t)((wm * 32 + (idx & 1) * 8 + (lane & 7)) * ROWB + ((idx >> 1) * 8) * 2);
    const uint32_t b_lm = (uint32_t)((wn * 64 + (idx >> 1) * 8 + (lane & 7)) * ROWB + ((idx & 1) * 8) * 2);

    float d[2][8][4];
    #pragma unroll
    for (int i = 0; i < 2; i++)
        #pragma unroll
        for (int j = 0; j < 8; j++)
            #pragma unroll
            for (int q = 0; q < 4; q++) d[i][j][q] = 0.f;

    // prefetch stage 0
    float4 aP[8];
    uint4  bP[4];
    #pragma unroll
    for (int i = 0; i < 8; i++)
        aP[i] = *reinterpret_cast<const float4*>(aBase + (size_t)(i * 16) * N_NODES);
    #pragma unroll
    for (int i = 0; i < 4; i++)
        bP[i] = *reinterpret_cast<const uint4*>(bBase + (size_t)(i * 32) * N_NODES);

    for (int s = 0; s < NSTAGES; s++) {
        const uint32_t bufb = (uint32_t)((s & 1) * BUFB);
        char* cbuf = smem + bufb;

        // ---- stage regs -> smem (fp32 -> fp16 for A) ----
        #pragma unroll
        for (int i = 0; i < 8; i++)
            *reinterpret_cast<uint2*>(cbuf + aSoff + i * (16 * ROWB)) = f4_to_h4(aP[i]);
        #pragma unroll
        for (int i = 0; i < 4; i++)
            *reinterpret_cast<uint4*>(cbuf + ATILE + bSoff + i * (32 * ROWB)) = bP[i];
        __syncthreads();

        // ---- prefetch next stage ----
        if (s + 1 < NSTAGES) {
            const int ko = (s + 1) * KSTAGE;
            #pragma unroll
            for (int i = 0; i < 8; i++)
                aP[i] = *reinterpret_cast<const float4*>(aBase + (size_t)(i * 16) * N_NODES + ko);
            #pragma unroll
            for (int i = 0; i < 4; i++)
                bP[i] = *reinterpret_cast<const uint4*>(bBase + (size_t)(i * 32) * N_NODES + ko);
        }

        // ---- MMA over this buffer ----
        const uint32_t sa = sbase + bufb;
        const uint32_t sbm = sa + ATILE;
        #pragma unroll
        for (int kk = 0; kk < 4; kk++) {
            uint32_t af[2][4], bf[4][4];
            #pragma unroll
            for (int mf = 0; mf < 2; mf++)
                LDSM4(af[mf], sa + a_lm + mf * (16 * ROWB) + kk * 32);
            #pragma unroll
            for (int nf = 0; nf < 4; nf++)
                LDSM4(bf[nf], sbm + b_lm + nf * (16 * ROWB) + kk * 32);
            #pragma unroll
            for (int mf = 0; mf < 2; mf++)
                #pragma unroll
                for (int nfr = 0; nfr < 8; nfr++)
                    MMAF16(d[mf][nfr], af[mf], bf[nfr >> 1][(nfr & 1) * 2], bf[nfr >> 1][(nfr & 1) * 2 + 1]);
        }
        __syncthreads();
    }

    // ---- epilogue: write partials ----
    const int g = lane >> 2, tg = lane & 3;
    #pragma unroll
    for (int mf = 0; mf < 2; mf++) {
        #pragma unroll
        for (int nfr = 0; nfr < 8; nfr++) {
            int m = m0 + wm * 32 + mf * 16 + g;
            int n = wn * 64 + nfr * 8 + tg * 2;
            float* o = pout + (size_t)m * DFEAT + n;
            *reinterpret_cast<float2*>(o) = make_float2(d[mf][nfr][0], d[mf][nfr][1]);
            *reinterpret_cast<float2*>(o + 8 * DFEAT) = make_float2(d[mf][nfr][2], d[mf][nfr][3]);
        }
    }
}

// ---------------------------------------------------------------------------
// Kernel 4: out[m][c] = dinv[m] * (p0 + p1)[m][c] + b[c]
// ---------------------------------------------------------------------------
__global__ void reduce_kernel(const float* __restrict__ p0, const float* __restrict__ p1,
                              const float* __restrict__ dinv, const float* __restrict__ bias,
                              float* __restrict__ out)
{
    int idx = blockIdx.x * blockDim.x + threadIdx.x;
    int e = idx << 2;
    int m = e >> 7, c = e & 127;
    float4 a = reinterpret_cast<const float4*>(p0)[idx];
    float4 b = reinterpret_cast<const float4*>(p1)[idx];
    float di = __ldg(&dinv[m]);
    float4 bb = *reinterpret_cast<const float4*>(bias + c);
    float4 o;
    o.x = di * (a.x + b.x) + bb.x;
    o.y = di * (a.y + b.y) + bb.y;
    o.z = di * (a.z + b.z) + bb.z;
    o.w = di * (a.w + b.w) + bb.w;
    reinterpret_cast<float4*>(out)[idx] = o;
}

// ---------------------------------------------------------------------------
// kernel_launch: inputs per metadata order: x, adj, W, b
// ---------------------------------------------------------------------------
extern "C" void kernel_launch(void* const* d_in, const int* in_sizes, int n_in,
                              void* d_out, int out_size) {
    const float* x   = (const float*)d_in[0];
    const float* adj = (const float*)d_in[1];
    const float* W   = (const float*)d_in[2];
    const float* b   = (const float*)d_in[3];
    float* out = (float*)d_out;

    float* dinv; cudaGetSymbolAddress((void**)&dinv, g_dinv);
    __half* zT;  cudaGetSymbolAddress((void**)&zT, g_zT);
    float* part; cudaGetSymbolAddress((void**)&part, g_part);

    cudaFuncSetAttribute(gcn_mma_kernel, cudaFuncAttributeMaxDynamicSharedMemorySize, SMEM_DYN);

    rowsum_kernel<<<N_NODES, 256>>>(adj, dinv);
    xw_kernel<<<N_NODES / 8, 256>>>(x, W, dinv, zT);
    gcn_mma_kernel<<<(N_NODES / BM) * KSPLIT, 256, SMEM_DYN>>>(adj, zT, part);
    reduce_kernel<<<(N_NODES * DFEAT / 4) / 256, 256>>>(part, part + (size_t)N_NODES * DFEAT,
                                                        dinv, b, out);
}